// round 6
// baseline (speedup 1.0000x reference)
#include <cuda_runtime.h>
#include <cuda_bf16.h>

#define NCLS 10
#define DIM  128
#define ACC_BLOCK    256               // 8 warps
#define ACC_GRID     296               // 2 blocks/SM * 148 SMs
#define NWARPS_TOT   (ACC_GRID * 8)    // 2368 warps
#define ENTRIES      (2 * NCLS * DIM)  // 2560: [sum(1280) | sq(1280)]

// Allocation-free scratch: per-block partial accumulators. No zeroing needed
// (each block overwrites its own slice every launch -> deterministic replay).
__device__ float        g_part[ACC_GRID * ENTRIES];   // ~3.0 MB, L2-resident
__device__ unsigned int g_pcnt[ACC_GRID * NCLS];
__device__ float        g_final[ENTRIES];

// ---------------------------------------------------------------------------
// Register accumulators per warp: class index is warp-uniform, so a uniform
// switch picks one of 10 register sets (lane l owns columns 4l..4l+3).
// ---------------------------------------------------------------------------
#define DECL_ACC(n) float4 s##n = {0,0,0,0}; float4 q##n = {0,0,0,0};

#define UPD(n, v) do {                                                   \
    s##n.x += (v).x; s##n.y += (v).y; s##n.z += (v).z; s##n.w += (v).w;  \
    q##n.x = fmaf((v).x,(v).x,q##n.x); q##n.y = fmaf((v).y,(v).y,q##n.y);\
    q##n.z = fmaf((v).z,(v).z,q##n.z); q##n.w = fmaf((v).w,(v).w,q##n.w);\
} while (0)

// counts packed 2-per-register (u16 halves); max per-warp count ~500 << 65536
#define PROC(v, c) do { switch (c) {                                     \
    case 0: UPD(0,(v)); cnt01 += 1u;       break;                        \
    case 1: UPD(1,(v)); cnt01 += 0x10000u; break;                        \
    case 2: UPD(2,(v)); cnt23 += 1u;       break;                        \
    case 3: UPD(3,(v)); cnt23 += 0x10000u; break;                        \
    case 4: UPD(4,(v)); cnt45 += 1u;       break;                        \
    case 5: UPD(5,(v)); cnt45 += 0x10000u; break;                        \
    case 6: UPD(6,(v)); cnt67 += 1u;       break;                        \
    case 7: UPD(7,(v)); cnt67 += 0x10000u; break;                        \
    case 8: UPD(8,(v)); cnt89 += 1u;       break;                        \
    case 9: UPD(9,(v)); cnt89 += 0x10000u; break;                        \
    default: break; } } while (0)

#define FOLD(n) do {                                                     \
    float4* p  = (float4*)(sh      + (n)*DIM + 4*lane);                  \
    float4* p2 = (float4*)(sh + NCLS*DIM + (n)*DIM + 4*lane);            \
    float4 a = *p;  a.x+=s##n.x; a.y+=s##n.y; a.z+=s##n.z; a.w+=s##n.w;  \
    *p = a;                                                              \
    float4 b = *p2; b.x+=q##n.x; b.y+=q##n.y; b.z+=q##n.z; b.w+=q##n.w;  \
    *p2 = b;                                                             \
} while (0)

__global__ __launch_bounds__(ACC_BLOCK, 2)
void CLIR_accum_kernel(const float* __restrict__ x,
                       const int*   __restrict__ t,
                       int N) {
    const int tid  = threadIdx.x;
    const int lane = tid & 31;
    const int warp = tid >> 5;                       // 0..7
    const int gw   = blockIdx.x * 8 + warp;          // global warp id

    DECL_ACC(0) DECL_ACC(1) DECL_ACC(2) DECL_ACC(3) DECL_ACC(4)
    DECL_ACC(5) DECL_ACC(6) DECL_ACC(7) DECL_ACC(8) DECL_ACC(9)
    unsigned cnt01 = 0, cnt23 = 0, cnt45 = 0, cnt67 = 0, cnt89 = 0;

    const float4* __restrict__ x4 = (const float4*)x;

    // 4 consecutive rows per warp per iteration: MLP=4 (4x LDG.128/lane),
    // labels as one aligned int4 load.
    for (int base = gw * 4; base < N; base += NWARPS_TOT * 4) {
        if (base + 4 <= N) {
            const int4 lab = __ldg((const int4*)(t + base));
            const float4 v0 = x4[(size_t)(base + 0) * (DIM/4) + lane];
            const float4 v1 = x4[(size_t)(base + 1) * (DIM/4) + lane];
            const float4 v2 = x4[(size_t)(base + 2) * (DIM/4) + lane];
            const float4 v3 = x4[(size_t)(base + 3) * (DIM/4) + lane];
            PROC(v0, lab.x);
            PROC(v1, lab.y);
            PROC(v2, lab.z);
            PROC(v3, lab.w);
        } else {
            for (int j = 0; base + j < N; j++) {
                const int c = __ldg(t + base + j);
                const float4 v = x4[(size_t)(base + j) * (DIM/4) + lane];
                PROC(v, c);
            }
        }
    }

    // --- Block epilogue: fold 8 warps into one smem copy (no atomics) ---
    __shared__ float        sh[ENTRIES];       // 10 KB, untouched in main loop
    __shared__ unsigned int shc[NCLS];

    for (int i = tid; i < ENTRIES; i += ACC_BLOCK) sh[i] = 0.0f;
    if (tid < NCLS) shc[tid] = 0u;
    __syncthreads();

    #pragma unroll 1
    for (int w = 0; w < 8; w++) {
        if (warp == w) {
            FOLD(0); FOLD(1); FOLD(2); FOLD(3); FOLD(4);
            FOLD(5); FOLD(6); FOLD(7); FOLD(8); FOLD(9);
            if (lane == 0) {
                shc[0] += cnt01 & 0xFFFFu;  shc[1] += cnt01 >> 16;
                shc[2] += cnt23 & 0xFFFFu;  shc[3] += cnt23 >> 16;
                shc[4] += cnt45 & 0xFFFFu;  shc[5] += cnt45 >> 16;
                shc[6] += cnt67 & 0xFFFFu;  shc[7] += cnt67 >> 16;
                shc[8] += cnt89 & 0xFFFFu;  shc[9] += cnt89 >> 16;
            }
        }
        __syncthreads();
    }

    // Coalesced partial write (overwrite, no init required)
    for (int i = tid; i < ENTRIES; i += ACC_BLOCK)
        g_part[blockIdx.x * ENTRIES + i] = sh[i];
    if (tid < NCLS)
        g_pcnt[blockIdx.x * NCLS + tid] = shc[tid];
}

// ---------------------------------------------------------------------------
// Fold 296 partial copies (fresh in L2) -> g_final. 20 blocks x 128 threads,
// coalesced 128B per warp per b-iteration, unrolled for MLP.
// ---------------------------------------------------------------------------
__global__ void CLIR_reduce_kernel() {
    const int e = blockIdx.x * 128 + threadIdx.x;   // 0..2559
    float acc = 0.0f;
    #pragma unroll 8
    for (int b = 0; b < ACC_GRID; b++)
        acc += g_part[b * ENTRIES + e];
    g_final[e] = acc;
}

__global__ void CLIR_finalize_kernel(float* __restrict__ out) {
    __shared__ float scnt[NCLS];
    const int d = threadIdx.x;                      // 128 threads
    if (d < NCLS) {
        unsigned cc = 0;
        #pragma unroll 8
        for (int b = 0; b < ACC_GRID; b++) cc += g_pcnt[b * NCLS + d];
        scnt[d] = (float)cc;
    }
    __syncthreads();

    float acc = 0.0f;
    #pragma unroll
    for (int c = 0; c < NCLS; c++) {
        const float n = scnt[c];
        const float s = g_final[c * DIM + d];
        const float q = g_final[NCLS * DIM + c * DIM + d];
        acc += (q - s * s / n) / (n - 1.0f);
    }
    #pragma unroll
    for (int o = 16; o > 0; o >>= 1)
        acc += __shfl_xor_sync(0xFFFFFFFFu, acc, o);
    __shared__ float wr[4];
    if ((d & 31) == 0) wr[d >> 5] = acc;
    __syncthreads();
    if (d == 0)
        out[0] = (wr[0] + wr[1] + wr[2] + wr[3]) * (1.0f / (float)NCLS);
}

extern "C" void kernel_launch(void* const* d_in, const int* in_sizes, int n_in,
                              void* d_out, int out_size) {
    const float* x = (const float*)d_in[0];
    const int*   t = (const int*)d_in[1];
    const int N = in_sizes[1];

    CLIR_accum_kernel<<<ACC_GRID, ACC_BLOCK>>>(x, t, N);
    CLIR_reduce_kernel<<<ENTRIES / 128, 128>>>();
    CLIR_finalize_kernel<<<1, DIM>>>((float*)d_out);
}

// round 8
// speedup vs baseline: 1.1120x; 1.1120x over previous
#include <cuda_runtime.h>
#include <cuda_bf16.h>
#include <cstdint>

#define NCLS 10
#define DIM  128
#define ROW_BYTES   512
#define GROUP_ROWS  4               // rows per cp.async group
#define STAGES      4               // ring slots (groups)
#define DEPTH       3               // groups in flight
#define BLOCK_WARPS 4
#define BLOCK_THREADS 128
#define GRID_BLOCKS 740             // 5 blocks/SM * 148 SMs
#define TOTAL_WARPS (GRID_BLOCKS * BLOCK_WARPS)   // 2960

#define WARP_DATA_BYTES (STAGES * GROUP_ROWS * ROW_BYTES)  // 8192
#define WARP_SMEM (WARP_DATA_BYTES + STAGES * 16)          // + label slots
#define NFINAL (NCLS * DIM + NCLS)   // 1280 sums + 10 class-S2 = 1290

// Allocation-free scratch. Zeroed by zero_kernel every launch (deterministic
// graph replay); accum blocks atomic-add their folded partials here.
__device__ float        g_final[NFINAL];
__device__ unsigned int g_cnt[NCLS];

__global__ void CLIR_zero_kernel() {
    int i = blockIdx.x * blockDim.x + threadIdx.x;
    if (i < NFINAL) g_final[i] = 0.0f;
    if (i < NCLS)   g_cnt[i] = 0u;
}

// ---- cp.async helpers -----------------------------------------------------
__device__ __forceinline__ uint32_t smem_u32(const void* p) {
    uint32_t a;
    asm("{ .reg .u64 t; cvta.to.shared.u64 t, %1; cvt.u32.u64 %0, t; }"
        : "=r"(a) : "l"(p));
    return a;
}
#define CP_ASYNC16(dst, src) \
    asm volatile("cp.async.cg.shared.global [%0], [%1], 16;\n" \
                 :: "r"(dst), "l"(src) : "memory")
#define CP_COMMIT() asm volatile("cp.async.commit_group;\n" ::: "memory")
#define CP_WAIT(n)  asm volatile("cp.async.wait_group %0;\n" :: "n"(n) : "memory")

// ---- per-class register accumulators (class is warp-uniform) --------------
#define DECL_ACC(n) float4 s##n = {0,0,0,0}; float q##n = 0.0f;

#define UPD(n, v) do {                                                   \
    s##n.x += (v).x; s##n.y += (v).y; s##n.z += (v).z; s##n.w += (v).w;  \
    float _d = fmaf((v).y,(v).y,(v).x*(v).x)                             \
             + fmaf((v).w,(v).w,(v).z*(v).z);                            \
    q##n += _d;                                                          \
} while (0)

#define PROC(v, c) do { switch (c) {                                     \
    case 0: UPD(0,(v)); cnt01 += 1u;       break;                        \
    case 1: UPD(1,(v)); cnt01 += 0x10000u; break;                        \
    case 2: UPD(2,(v)); cnt23 += 1u;       break;                        \
    case 3: UPD(3,(v)); cnt23 += 0x10000u; break;                        \
    case 4: UPD(4,(v)); cnt45 += 1u;       break;                        \
    case 5: UPD(5,(v)); cnt45 += 0x10000u; break;                        \
    case 6: UPD(6,(v)); cnt67 += 1u;       break;                        \
    case 7: UPD(7,(v)); cnt67 += 0x10000u; break;                        \
    case 8: UPD(8,(v)); cnt89 += 1u;       break;                        \
    case 9: UPD(9,(v)); cnt89 += 0x10000u; break;                        \
    default: break; } } while (0)

#define FOLDC(n) do {                                                    \
    atomicAdd(&fold[(n)*DIM + 4*lane + 0], s##n.x);                      \
    atomicAdd(&fold[(n)*DIM + 4*lane + 1], s##n.y);                      \
    atomicAdd(&fold[(n)*DIM + 4*lane + 2], s##n.z);                      \
    atomicAdd(&fold[(n)*DIM + 4*lane + 3], s##n.w);                      \
    atomicAdd(&fold[NCLS*DIM + (n)], q##n);                              \
} while (0)

__global__ __launch_bounds__(BLOCK_THREADS, 5)
void CLIR_accum_kernel(const float* __restrict__ x,
                       const int*   __restrict__ t,
                       int N) {
    __shared__ __align__(16) unsigned char smem_raw[BLOCK_WARPS * WARP_SMEM];

    const int tid  = threadIdx.x;
    const int lane = tid & 31;
    const int warp = tid >> 5;
    const int gw   = blockIdx.x * BLOCK_WARPS + warp;   // global warp id
    const int NG   = (N + GROUP_ROWS - 1) / GROUP_ROWS; // total groups

    const uint32_t sbase = smem_u32(smem_raw) + warp * WARP_SMEM;
    unsigned char* warp_smem = smem_raw + warp * WARP_SMEM;

    DECL_ACC(0) DECL_ACC(1) DECL_ACC(2) DECL_ACC(3) DECL_ACC(4)
    DECL_ACC(5) DECL_ACC(6) DECL_ACC(7) DECL_ACC(8) DECL_ACC(9)
    unsigned cnt01 = 0, cnt23 = 0, cnt45 = 0, cnt67 = 0, cnt89 = 0;

    // Issue one group's cp.async copies into ring stage st (no commit here).
    auto issue = [&](int g, int st) {
        const int r0 = g * GROUP_ROWS;
        const uint32_t dst0 = sbase + st * (GROUP_ROWS * ROW_BYTES) + lane * 16;
        const float* src0 = x + (size_t)r0 * DIM + lane * 4;
        #pragma unroll
        for (int j = 0; j < GROUP_ROWS; j++)
            if (r0 + j < N)
                CP_ASYNC16(dst0 + j * ROW_BYTES, src0 + (size_t)j * DIM);
        if (lane == 0 && r0 + GROUP_ROWS <= N)
            CP_ASYNC16(sbase + WARP_DATA_BYTES + st * 16, t + r0);
    };

    // Prologue: DEPTH groups in flight in stages 0..DEPTH-1 (guards make
    // overrun groups empty; commits unconditional so group accounting is
    // uniform across threads).
    #pragma unroll
    for (int p = 0; p < DEPTH; p++) {
        const int g = gw + p * TOTAL_WARPS;
        if (g < NG) issue(g, p);
        CP_COMMIT();
    }

    int st = 0;
    for (int g = gw; g < NG; g += TOTAL_WARPS, st = (st + 1) & (STAGES - 1)) {
        CP_WAIT(DEPTH - 1);        // oldest group (this stage) complete
        __syncwarp();              // lane0's label copy visible to all lanes

        const int r0 = g * GROUP_ROWS;
        const float4* slot =
            (const float4*)(warp_smem + st * (GROUP_ROWS * ROW_BYTES)) + lane;

        if (r0 + GROUP_ROWS <= N) {
            const int4 lab = *(const int4*)(warp_smem + WARP_DATA_BYTES + st * 16);
            const float4 v0 = slot[0 * 32];
            const float4 v1 = slot[1 * 32];
            const float4 v2 = slot[2 * 32];
            const float4 v3 = slot[3 * 32];
            PROC(v0, lab.x);
            PROC(v1, lab.y);
            PROC(v2, lab.z);
            PROC(v3, lab.w);
        } else {   // partial tail group: labels straight from gmem
            for (int j = 0; r0 + j < N; j++) {
                const int c = __ldg(t + r0 + j);
                const float4 v = slot[j * 32];
                PROC(v, c);
            }
        }

        // FIX (R7 bug): refill the FREE stage (st+DEPTH), not the one just
        // consumed. Ring: consume st, stages st+1..st+DEPTH-1 in flight,
        // st+DEPTH empty -> fill it.
        const int gn = g + DEPTH * TOTAL_WARPS;
        if (gn < NG) issue(gn, (st + DEPTH) & (STAGES - 1));
        CP_COMMIT();               // unconditional: keeps wait depth uniform
    }
    CP_WAIT(0);
    __syncthreads();

    // ---- Block fold (smem aliases the ring; safe after the barrier) ----
    float* fold = (float*)smem_raw;                       // NFINAL floats
    unsigned* foldc = (unsigned*)(smem_raw + ((NFINAL * 4 + 15) & ~15));
    for (int i = tid; i < NFINAL; i += BLOCK_THREADS) fold[i] = 0.0f;
    if (tid < NCLS) foldc[tid] = 0u;
    __syncthreads();

    FOLDC(0); FOLDC(1); FOLDC(2); FOLDC(3); FOLDC(4);
    FOLDC(5); FOLDC(6); FOLDC(7); FOLDC(8); FOLDC(9);
    if (lane == 0) {
        atomicAdd(&foldc[0], cnt01 & 0xFFFFu); atomicAdd(&foldc[1], cnt01 >> 16);
        atomicAdd(&foldc[2], cnt23 & 0xFFFFu); atomicAdd(&foldc[3], cnt23 >> 16);
        atomicAdd(&foldc[4], cnt45 & 0xFFFFu); atomicAdd(&foldc[5], cnt45 >> 16);
        atomicAdd(&foldc[6], cnt67 & 0xFFFFu); atomicAdd(&foldc[7], cnt67 >> 16);
        atomicAdd(&foldc[8], cnt89 & 0xFFFFu); atomicAdd(&foldc[9], cnt89 >> 16);
    }
    __syncthreads();

    // ---- Global spread atomics (REDG): 1290 + 10 per block ----
    for (int i = tid; i < NFINAL; i += BLOCK_THREADS)
        atomicAdd(&g_final[i], fold[i]);
    if (tid < NCLS)
        atomicAdd(&g_cnt[tid], foldc[tid]);
}

// penalty = (1/C) * Σ_c [ S2_c/(n_c-1) - Σ_d sum[c][d]^2 / (n_c (n_c-1)) ]
__global__ void CLIR_finalize_kernel(float* __restrict__ out) {
    __shared__ float scnt[NCLS];
    const int d = threadIdx.x;   // 128 threads
    if (d < NCLS) scnt[d] = (float)g_cnt[d];
    __syncthreads();

    float p = 0.0f;
    #pragma unroll
    for (int c = 0; c < NCLS; c++) {
        const float n = scnt[c];
        const float s = g_final[c * DIM + d];
        p += (s * s) / (n * (n - 1.0f));
    }
    #pragma unroll
    for (int o = 16; o > 0; o >>= 1)
        p += __shfl_xor_sync(0xFFFFFFFFu, p, o);
    __shared__ float wr[4];
    if ((d & 31) == 0) wr[d >> 5] = p;
    __syncthreads();
    if (d == 0) {
        float tr = 0.0f;
        #pragma unroll
        for (int c = 0; c < NCLS; c++)
            tr += g_final[NCLS * DIM + c] / (scnt[c] - 1.0f);
        out[0] = (tr - (wr[0] + wr[1] + wr[2] + wr[3])) * (1.0f / (float)NCLS);
    }
}

extern "C" void kernel_launch(void* const* d_in, const int* in_sizes, int n_in,
                              void* d_out, int out_size) {
    const float* x = (const float*)d_in[0];
    const int*   t = (const int*)d_in[1];
    const int N = in_sizes[1];

    CLIR_zero_kernel<<<(NFINAL + 255) / 256, 256>>>();
    CLIR_accum_kernel<<<GRID_BLOCKS, BLOCK_THREADS>>>(x, t, N);
    CLIR_finalize_kernel<<<1, DIM>>>((float*)d_out);
}